// round 16
// baseline (speedup 1.0000x reference)
#include <cuda_runtime.h>
#include <cuda_fp16.h>
#include <cstdint>
#include <math.h>

#define BATCH 1024
#define TSTEPS 12
#define TAU 0.25f
#define BK 64                   // K halfs per stage (raw GEMM)
#define SROW 72                 // raw smem row stride (halfs)
#define ASTG   (128 * SROW * 2) // 18432
#define BSTG128 (128 * SROW * 2)
// step kernel: BK=128 stages, warp-split-K
#define SROW2 136               // 128-half rows + pad (272B) — conflict-free
#define A2STG (64 * SROW2 * 2)  // 17408
#define B2STG (96 * SROW2 * 2)  // 26112
#define SMEM_STEP2 (2 * (A2STG + B2STG))   // 87040

// ---------------- static scratch ----------------
__device__ __align__(256) __half g_Xh[(size_t)BATCH * TSTEPS * 1024];
__device__ __align__(256) __half g_Uh[(size_t)11 * BATCH * 1024];
__device__ __align__(256) __half g_V[(size_t)TSTEPS * BATCH * 1024];   // fp16 V
__device__ __align__(256) __half g_ah[TSTEPS][(size_t)BATCH * 1024];
__device__ __align__(256) __half g_apc[2][(size_t)BATCH * 1536];
__device__ __align__(256) float  g_psc[2][(size_t)BATCH * 1536];
__device__ __align__(256) __half g_Ws[(size_t)1536 * 1536];
__device__ __align__(256) __half g_Whp[(size_t)1024 * 1024];
__device__ __align__(256) __half g_Woh[(size_t)1024 * 1024];
__device__ __align__(256) float  g_biaspc[1536];
__device__ __align__(256) float  g_psc0[1536];
__device__ __align__(256) __half g_apc0h[1536];
__device__ __align__(256) float  g_q1[1536];

// ---------------- helpers ----------------
__device__ __forceinline__ uint32_t smem_u32(const void* p) {
    uint32_t a;
    asm("{ .reg .u64 t; cvta.to.shared.u64 t, %1; cvt.u32.u64 %0, t; }" : "=r"(a) : "l"(p));
    return a;
}
#define CP_ASYNC16(dst, src) \
    asm volatile("cp.async.cg.shared.global [%0], [%1], 16;" :: "r"(dst), "l"(src))
#define CP_COMMIT() asm volatile("cp.async.commit_group;" ::: "memory")
#define CP_WAIT(n)  asm volatile("cp.async.wait_group %0;" :: "n"(n) : "memory")

#define LDSM_X4(r0, r1, r2, r3, a) \
    asm volatile("ldmatrix.sync.aligned.m8n8.x4.shared.b16 {%0,%1,%2,%3}, [%4];" \
                 : "=r"(r0), "=r"(r1), "=r"(r2), "=r"(r3) : "r"(a))

__device__ __forceinline__ void mma_f16(float* d, const uint32_t* a, const uint32_t* b) {
    asm volatile(
        "mma.sync.aligned.m16n8k16.row.col.f32.f16.f16.f32 "
        "{%0,%1,%2,%3}, {%4,%5,%6,%7}, {%8,%9}, {%0,%1,%2,%3};"
        : "+f"(d[0]), "+f"(d[1]), "+f"(d[2]), "+f"(d[3])
        : "r"(a[0]), "r"(a[1]), "r"(a[2]), "r"(a[3]), "r"(b[0]), "r"(b[1]));
}
__device__ __forceinline__ float sigm(float x) { return 1.0f / (1.0f + expf(-x)); }

// ---------------- raw GEMM (128x128, 2-stage, 2 CTA/SM) — measured 77us ------
struct GDescRaw {
    const __half* A; int lda; int rowperm;
    const __half* BT; int ldb;
    int nk;
    int N; int grid_n;
    float* out_f32;
    __half* out_f16;
};

__global__ __launch_bounds__(256, 2)
void tc_gemm_raw(GDescRaw d) {
    extern __shared__ __align__(16) char smem[];
    const uint32_t sA = smem_u32(smem);
    const uint32_t sB = sA + 2 * ASTG;
    const int bm = blockIdx.x / d.grid_n;
    const int bn = blockIdx.x % d.grid_n;
    const int tid = threadIdx.x;
    const int warp = tid >> 5, lane = tid & 31;
    const int wm = warp >> 1, wn = warp & 1;
    const int g = lane >> 2, tg = lane & 3;

    const size_t arow = (size_t)bm * 128;
    const size_t brow = (size_t)bn * 128;

    float acc[2][8][4];
#pragma unroll
    for (int i = 0; i < 2; ++i)
#pragma unroll
        for (int j = 0; j < 8; ++j)
#pragma unroll
            for (int k = 0; k < 4; ++k) acc[i][j][k] = 0.0f;

    const int lrow = tid >> 3;
    const int lch  = (tid & 7) << 3;

    auto load_stage = [&](int kc, int s) {
        const int kbase = kc * BK;
#pragma unroll
        for (int i = 0; i < 4; ++i) {
            size_t r = arow + lrow + 32 * i;
            if (d.rowperm) { size_t b = r & 1023, t = r >> 10; r = b * 12 + t; }
            CP_ASYNC16(sA + s * ASTG + (uint32_t)((lrow + 32 * i) * SROW + lch) * 2u,
                       d.A + r * (size_t)d.lda + kbase + lch);
        }
#pragma unroll
        for (int i = 0; i < 4; ++i) {
            int r = lrow + 32 * i;
            CP_ASYNC16(sB + s * BSTG128 + (uint32_t)(r * SROW + lch) * 2u,
                       d.BT + (brow + r) * (size_t)d.ldb + kbase + lch);
        }
        CP_COMMIT();
    };

    const uint32_t aLane =
        (uint32_t)(((wm * 32) + (((lane >> 3) & 1) << 3) + (lane & 7)) * SROW +
                   ((lane >> 4) << 3)) * 2u;
    const uint32_t bLane =
        (uint32_t)(((wn * 64) + (((lane >> 4) & 1) << 3) + (lane & 7)) * SROW +
                   (((lane >> 3) & 1) << 3)) * 2u;

    auto compute_stage = [&](int s) {
        const uint32_t aOff = sA + s * ASTG + aLane;
        const uint32_t bOff = sB + s * BSTG128 + bLane;
#pragma unroll
        for (int k16 = 0; k16 < BK / 16; ++k16) {
            uint32_t af[2][4], bf[4][4];
#pragma unroll
            for (int mt = 0; mt < 2; ++mt)
                LDSM_X4(af[mt][0], af[mt][1], af[mt][2], af[mt][3],
                        aOff + mt * 16 * SROW * 2 + k16 * 32);
#pragma unroll
            for (int np = 0; np < 4; ++np)
                LDSM_X4(bf[np][0], bf[np][1], bf[np][2], bf[np][3],
                        bOff + np * 16 * SROW * 2 + k16 * 32);
#pragma unroll
            for (int mt = 0; mt < 2; ++mt)
#pragma unroll
                for (int nt = 0; nt < 8; ++nt)
                    mma_f16(acc[mt][nt], af[mt], &bf[nt >> 1][(nt & 1) * 2]);
        }
    };

    load_stage(0, 0);
    const int nk = d.nk;
    for (int kc = 0; kc < nk; ++kc) {
        if (kc + 1 < nk) {
            load_stage(kc + 1, (kc + 1) & 1);
            CP_WAIT(1);
        } else {
            CP_WAIT(0);
        }
        __syncthreads();
        compute_stage(kc & 1);
        __syncthreads();
    }

    const int N = d.N;
#pragma unroll
    for (int mt = 0; mt < 2; ++mt) {
        const int r0 = bm * 128 + wm * 32 + mt * 16 + g;
#pragma unroll
        for (int nt = 0; nt < 8; ++nt) {
            const int c0 = bn * 128 + wn * 64 + nt * 8 + tg * 2;
            if (d.out_f32) {
                float* o0 = d.out_f32 + (size_t)r0 * N + c0;
                *(float2*)o0 = make_float2(acc[mt][nt][0], acc[mt][nt][1]);
                *(float2*)(o0 + (size_t)8 * N) = make_float2(acc[mt][nt][2], acc[mt][nt][3]);
            } else {
                __half* o0 = d.out_f16 + (size_t)r0 * N + c0;
                *(__half2*)o0 = __floats2half2_rn(acc[mt][nt][0], acc[mt][nt][1]);
                *(__half2*)(o0 + (size_t)8 * N) = __floats2half2_rn(acc[mt][nt][2], acc[mt][nt][3]);
            }
        }
    }
}

// ---------------- step kernel (t=2..11): 64x96 tile, warp-split-K, 256 CTAs ---
// 8 warps: wk = K-half (k16 0-3 / 4-7 of a BK=128 stage), each warp 32x48.
// Cross-warp partial reduction via smem after mainloop.
__global__ __launch_bounds__(256, 2)
void tc_step(int t, float* __restrict__ out) {
    constexpr int NT = 6;
    extern __shared__ __align__(16) char smem[];
    const uint32_t sA = smem_u32(smem);                 // 2 x A2STG
    const uint32_t sB = sA + 2 * A2STG;                 // 2 x B2STG
    const int bm = blockIdx.x >> 4;      // 0..15 (M/64)
    const int bn = blockIdx.x & 15;      // 0..15 (1536/96)
    const int tid = threadIdx.x;
    const int warp = tid >> 5, lane = tid & 31;
    const int wk = warp >> 2;            // K half
    const int wm = (warp >> 1) & 1;      // 32-row slice
    const int wn = warp & 1;             // 48-col slice
    const int g = lane >> 2, tg = lane & 3;
    const int rd = t & 1, wr = rd ^ 1;

    const __half* __restrict__ A = g_apc[rd];
    const size_t arow = (size_t)bm * 64;
    const size_t brow = (size_t)bn * 96;
    const int nk = (bn >= 11) ? 8 : 12;  // BK=128 chunks; c-tiles skip zero block

    float acc[2][NT][4];
#pragma unroll
    for (int i = 0; i < 2; ++i)
#pragma unroll
        for (int j = 0; j < NT; ++j)
#pragma unroll
            for (int k = 0; k < 4; ++k) acc[i][j][k] = 0.0f;

    auto load_stage = [&](int kc, int s) {
        const int kbase = kc * 128;
#pragma unroll
        for (int i = 0; i < 4; ++i) {      // A: 64 rows x 16 chunks
            int idx = tid + 256 * i;
            int r = idx >> 4, ch = (idx & 15) << 3;
            CP_ASYNC16(sA + s * A2STG + (uint32_t)(r * SROW2 + ch) * 2u,
                       A + (arow + r) * 1536 + kbase + ch);
        }
#pragma unroll
        for (int i = 0; i < 6; ++i) {      // B: 96 rows x 16 chunks
            int idx = tid + 256 * i;
            int r = idx >> 4, ch = (idx & 15) << 3;
            CP_ASYNC16(sB + s * B2STG + (uint32_t)(r * SROW2 + ch) * 2u,
                       g_Ws + (brow + r) * (size_t)1536 + kbase + ch);
        }
        CP_COMMIT();
    };

    const uint32_t aLane =
        (uint32_t)(((wm * 32) + (((lane >> 3) & 1) << 3) + (lane & 7)) * SROW2 +
                   ((lane >> 4) << 3)) * 2u;
    const uint32_t bLane =
        (uint32_t)(((wn * 48) + (((lane >> 4) & 1) << 3) + (lane & 7)) * SROW2 +
                   (((lane >> 3) & 1) << 3)) * 2u;
    const uint32_t kOff = (uint32_t)(wk * 64) * 2u;    // 64 halfs into the 128-half stage

    auto compute_stage = [&](int s) {
        const uint32_t aOff = sA + s * A2STG + aLane + kOff;
        const uint32_t bOff = sB + s * B2STG + bLane + kOff;
#pragma unroll
        for (int j = 0; j < 4; ++j) {      // 4 k16 per warp per stage
            uint32_t af[2][4], bf[3][4];
#pragma unroll
            for (int mt = 0; mt < 2; ++mt)
                LDSM_X4(af[mt][0], af[mt][1], af[mt][2], af[mt][3],
                        aOff + mt * 16 * SROW2 * 2 + j * 32);
#pragma unroll
            for (int np = 0; np < 3; ++np)
                LDSM_X4(bf[np][0], bf[np][1], bf[np][2], bf[np][3],
                        bOff + np * 16 * SROW2 * 2 + j * 32);
#pragma unroll
            for (int mt = 0; mt < 2; ++mt)
#pragma unroll
                for (int nt = 0; nt < NT; ++nt)
                    mma_f16(acc[mt][nt], af[mt], &bf[nt >> 1][(nt & 1) * 2]);
        }
    };

    load_stage(0, 0);
    for (int kc = 0; kc < nk; ++kc) {
        if (kc + 1 < nk) {
            load_stage(kc + 1, (kc + 1) & 1);
            CP_WAIT(1);
        } else {
            CP_WAIT(0);
        }
        __syncthreads();
        compute_stage(kc & 1);
        __syncthreads();     // final iteration: all warps done with smem
    }

    // ---- cross-warp K reduction (reuse pipeline smem; safe after last barrier)
    float* rbuf = (float*)smem;          // 64 x 96, row stride 100 floats (25.6KB)
    if (wk == 1) {
#pragma unroll
        for (int mt = 0; mt < 2; ++mt)
#pragma unroll
            for (int nt = 0; nt < NT; ++nt)
#pragma unroll
                for (int h = 0; h < 2; ++h) {
                    int r = wm * 32 + mt * 16 + g + 8 * h;
                    int c = wn * 48 + nt * 8 + tg * 2;
                    *(float2*)&rbuf[r * 100 + c] =
                        make_float2(acc[mt][nt][2 * h + 0], acc[mt][nt][2 * h + 1]);
                }
    }
    __syncthreads();
    if (wk == 1) return;                 // partner warps finished

    const __half* __restrict__ Vt = g_V + (size_t)t * (BATCH * 1024);
    const float* __restrict__ prev = g_psc[rd];
    float* __restrict__ st = g_psc[wr];
    __half* __restrict__ act = g_apc[wr];
    float* __restrict__ extra =
        (t >= TSTEPS - 4) ? out + (size_t)(t - (TSTEPS - 4)) * BATCH * 1024 : nullptr;

#pragma unroll
    for (int mt = 0; mt < 2; ++mt) {
        const int r0 = bm * 64 + wm * 32 + mt * 16 + g;
#pragma unroll
        for (int nt = 0; nt < NT; ++nt) {
            const int c0 = bn * 96 + wn * 48 + nt * 8 + tg * 2;
            const bool isP = c0 < 1024;
            float2 bv = *(const float2*)(g_biaspc + c0);
#pragma unroll
            for (int h = 0; h < 2; ++h) {
                const int r = r0 + 8 * h;
                const int rl = wm * 32 + mt * 16 + g + 8 * h;
                const int cl = wn * 48 + nt * 8 + tg * 2;
                float2 po = *(const float2*)&rbuf[rl * 100 + cl];
                const size_t off = (size_t)r * 1536 + c0;
                float2 pv = *(const float2*)(prev + off);
                float2 vv = make_float2(0.f, 0.f);
                if (isP) vv = __half22float2(*(const __half2*)(Vt + (size_t)r * 1024 + c0));
                float2 v, a;
                v.x = TAU * (acc[mt][nt][2 * h + 0] + po.x + vv.x + bv.x) + (1.0f - TAU) * pv.x;
                v.y = TAU * (acc[mt][nt][2 * h + 1] + po.y + vv.y + bv.y) + (1.0f - TAU) * pv.y;
                a.x = sigm(v.x);
                a.y = sigm(v.y);
                *(float2*)(st + off) = v;
                *(__half2*)(act + off) = __floats2half2_rn(a.x, a.y);
                if (extra && isP)
                    *(float2*)(extra + (size_t)r * 1024 + c0) = a;
            }
        }
    }
}

// ---------------- prep kernels ----------------
__global__ void prep_misc(const float* __restrict__ inputs,
                          const float* __restrict__ bias_p,
                          const float* __restrict__ bias_c) {
    int i = blockIdx.x * blockDim.x + threadIdx.x;
    const int n8 = BATCH * TSTEPS * 1024 / 8;
    if (i < n8) {
        float4 a = ((const float4*)inputs)[2 * i];
        float4 b = ((const float4*)inputs)[2 * i + 1];
        __half2 h0 = __floats2half2_rn(a.x, a.y);
        __half2 h1 = __floats2half2_rn(a.z, a.w);
        __half2 h2 = __floats2half2_rn(b.x, b.y);
        __half2 h3 = __floats2half2_rn(b.z, b.w);
        uint4 o;
        o.x = *(uint32_t*)&h0; o.y = *(uint32_t*)&h1;
        o.z = *(uint32_t*)&h2; o.w = *(uint32_t*)&h3;
        ((uint4*)g_Xh)[i] = o;
    }
    if (i < 1536) g_biaspc[i] = (i < 1024) ? bias_p[i] : bias_c[i - 1024];
    if (i < 512 * 512 / 8) {   // zero g_Ws c-rows, K in [1024,1536)
        int row = 1024 + (i >> 6);
        int col = 1024 + (i & 63) * 8;
        *(uint4*)(g_Ws + (size_t)row * 1536 + col) = make_uint4(0, 0, 0, 0);
    }
}

__global__ void prep_tr(const float* __restrict__ w_oh, const float* __restrict__ w_hp,
                        const float* __restrict__ w_pp, const float* __restrict__ w_pc,
                        const float* __restrict__ w_cp) {
    __shared__ float t[32][33];
    const int z = blockIdx.z;
    const float* src; __half* dst; int K, N, ldd, koff;
    switch (z) {
        case 0: src = w_oh; dst = g_Woh; K = 1024; N = 1024; ldd = 1024; koff = 0;    break;
        case 1: src = w_hp; dst = g_Whp; K = 1024; N = 1024; ldd = 1024; koff = 0;    break;
        case 2: src = w_pp; dst = g_Ws;  K = 1024; N = 1024; ldd = 1536; koff = 0;    break;
        case 3: src = w_cp; dst = g_Ws;  K =  512; N = 1024; ldd = 1536; koff = 1024; break;
        default: src = w_pc; dst = g_Ws + (size_t)1024 * 1536;
                 K = 1024; N = 512; ldd = 1536; koff = 0; break;
    }
    int n0 = blockIdx.x * 32, k0 = blockIdx.y * 32;
    if (n0 >= N || k0 >= K) return;
    int tx = threadIdx.x, ty = threadIdx.y;
#pragma unroll
    for (int i = 0; i < 4; ++i)
        t[ty + 8 * i][tx] = src[(size_t)(k0 + ty + 8 * i) * N + n0 + tx];
    __syncthreads();
#pragma unroll
    for (int i = 0; i < 4; ++i)
        dst[(size_t)(n0 + ty + 8 * i) * ldd + koff + k0 + tx] = __float2half_rn(t[tx][ty + 8 * i]);
}

// step-0 constants via row sums of the transposed fp16 weights (coalesced).
__global__ void colsum2_kernel() {
    int row = blockIdx.x * 8 + (threadIdx.x >> 5);
    int lane = threadIdx.x & 31;
    if (row >= 1536) return;
    const __half2* w = (const __half2*)(g_Ws + (size_t)row * 1536);
    float s = 0.f;
    for (int k = lane; k < 768; k += 32) {
        float2 wv = __half22float2(w[k]);
        s += wv.x + wv.y;
    }
    if (row < 1024) {
        const __half2* w2 = (const __half2*)(g_Whp + (size_t)row * 1024);
        for (int k = lane; k < 512; k += 32) {
            float2 wv = __half22float2(w2[k]);
            s += wv.x + wv.y;
        }
    }
#pragma unroll
    for (int o = 16; o; o >>= 1) s += __shfl_xor_sync(0xFFFFFFFFu, s, o);
    if (lane == 0) {
        float v = TAU * (0.5f * s + g_biaspc[row]);
        g_psc0[row] = v;
        g_apc0h[row] = __float2half_rn(sigm(v));
    }
}

// q1[n] = apc0 . Ws[n,:]  (warp per row)
__global__ void q1_kernel() {
    int row = blockIdx.x * 8 + (threadIdx.x >> 5);
    int lane = threadIdx.x & 31;
    if (row >= 1536) return;
    const __half2* w = (const __half2*)(g_Ws + (size_t)row * 1536);
    const __half2* a = (const __half2*)g_apc0h;
    float s = 0.f;
    for (int k = lane; k < 768; k += 32) {
        float2 wv = __half22float2(w[k]);
        float2 av = __half22float2(a[k]);
        s += wv.x * av.x + wv.y * av.y;
    }
#pragma unroll
    for (int o = 16; o; o >>= 1) s += __shfl_xor_sync(0xFFFFFFFFu, s, o);
    if (lane == 0) g_q1[row] = s;
}

// step 1 (elementwise)
__global__ void step1_ew() {
    int idx = blockIdx.x * blockDim.x + threadIdx.x;   // B*384
    if (idx >= BATCH * 384) return;
    int b = idx / 384, c4 = (idx % 384) * 4;
    float4 q = *(const float4*)(g_q1 + c4);
    float4 bi = *(const float4*)(g_biaspc + c4);
    float4 p0 = *(const float4*)(g_psc0 + c4);
    float4 vv = make_float4(0.f, 0.f, 0.f, 0.f);
    if (c4 < 1024) {
        uint2 vh = *(const uint2*)(g_V + (size_t)BATCH * 1024 + (size_t)b * 1024 + c4);
        float2 lo = __half22float2(*(const __half2*)&vh.x);
        float2 hi = __half22float2(*(const __half2*)&vh.y);
        vv = make_float4(lo.x, lo.y, hi.x, hi.y);
    }
    float4 v;
    v.x = TAU * (vv.x + q.x + bi.x) + (1.0f - TAU) * p0.x;
    v.y = TAU * (vv.y + q.y + bi.y) + (1.0f - TAU) * p0.y;
    v.z = TAU * (vv.z + q.z + bi.z) + (1.0f - TAU) * p0.z;
    v.w = TAU * (vv.w + q.w + bi.w) + (1.0f - TAU) * p0.w;
    *(float4*)(g_psc[0] + (size_t)b * 1536 + c4) = v;
    __half2 lo = __floats2half2_rn(sigm(v.x), sigm(v.y));
    __half2 hi = __floats2half2_rn(sigm(v.z), sigm(v.w));
    uint2 o; o.x = *(uint32_t*)&lo; o.y = *(uint32_t*)&hi;
    *(uint2*)(g_apc[0] + (size_t)b * 1536 + c4) = o;
}

// h-scan over fp16 U (t-major): slot t+1 <- sigmoid(h_t), t=0..10
__global__ void hscan_kernel(const float* __restrict__ bias_h) {
    int i = blockIdx.x * blockDim.x + threadIdx.x;   // B*128
    if (i >= BATCH * 128) return;
    int b = i >> 7, h8 = (i & 127) << 3;
    float bh[8];
    *(float4*)&bh[0] = *(const float4*)(bias_h + h8);
    *(float4*)&bh[4] = *(const float4*)(bias_h + h8 + 4);
    float hh[8];
#pragma unroll
    for (int j = 0; j < 8; ++j) hh[j] = 0.f;
#pragma unroll
    for (int t = 0; t < 11; ++t) {
        uint4 u4 = *(const uint4*)(g_Uh + ((size_t)(t * 1024 + b) << 10) + h8);
        const __half2* uh = (const __half2*)&u4;
        uint4 o;
        uint32_t* op = (uint32_t*)&o;
#pragma unroll
        for (int j = 0; j < 4; ++j) {
            float2 u = __half22float2(uh[j]);
            hh[2 * j + 0] = TAU * (u.x + bh[2 * j + 0]) + (1.0f - TAU) * hh[2 * j + 0];
            hh[2 * j + 1] = TAU * (u.y + bh[2 * j + 1]) + (1.0f - TAU) * hh[2 * j + 1];
            __half2 s = __floats2half2_rn(sigm(hh[2 * j + 0]), sigm(hh[2 * j + 1]));
            op[j] = *(uint32_t*)&s;
        }
        *(uint4*)(g_ah[t + 1] + (size_t)b * 1024 + h8) = o;
    }
}

// ---------------- launch ----------------
extern "C" void kernel_launch(void* const* d_in, const int* in_sizes, int n_in,
                              void* d_out, int out_size) {
    const float* inputs = (const float*)d_in[0];
    const float* w_oh   = (const float*)d_in[1];
    const float* w_hp   = (const float*)d_in[2];
    const float* w_pp   = (const float*)d_in[3];
    const float* w_pc   = (const float*)d_in[4];
    const float* w_cp   = (const float*)d_in[5];
    const float* bias_h = (const float*)d_in[6];
    const float* bias_p = (const float*)d_in[7];
    const float* bias_c = (const float*)d_in[8];
    float* out = (float*)d_out;                    // [4, B, 1024]

    __half *Xh, *Uh, *ah, *V, *Whp, *Woh;
    cudaGetSymbolAddress((void**)&Xh,  g_Xh);
    cudaGetSymbolAddress((void**)&Uh,  g_Uh);
    cudaGetSymbolAddress((void**)&ah,  g_ah);
    cudaGetSymbolAddress((void**)&V,   g_V);
    cudaGetSymbolAddress((void**)&Whp, g_Whp);
    cudaGetSymbolAddress((void**)&Woh, g_Woh);

    const int SMEM_RAW = 2 * (ASTG + BSTG128);    // 73728
    cudaFuncSetAttribute(tc_gemm_raw, cudaFuncAttributeMaxDynamicSharedMemorySize, SMEM_RAW);
    cudaFuncSetAttribute(tc_step, cudaFuncAttributeMaxDynamicSharedMemorySize, SMEM_STEP2);

    // 0) prep
    prep_misc<<<(BATCH * TSTEPS * 1024 / 8 + 255) / 256, 256>>>(inputs, bias_p, bias_c);
    prep_tr<<<dim3(32, 32, 5), dim3(32, 8)>>>(w_oh, w_hp, w_pp, w_pc, w_cp);
    colsum2_kernel<<<192, 256>>>();

    // 1) U GEMM (t-major rows t*1024+b, t=0..10): Uh = Xh @ w_oh, fp16 out
    {
        GDescRaw du = {};
        du.A = Xh; du.lda = 1024; du.rowperm = 1;
        du.BT = Woh; du.ldb = 1024; du.nk = 1024 / BK;
        du.N = 1024; du.grid_n = 8;
        du.out_f16 = Uh;
        tc_gemm_raw<<<(11 * 1024 / 128) * 8, 256, SMEM_RAW>>>(du);   // 704 CTAs
    }

    // 2) h-scan -> a_h slots 1..11
    hscan_kernel<<<(BATCH * 128 + 255) / 256, 256>>>(bias_h);

    // 3) V GEMM for t=1..11: V[t] = ah[slot t] @ w_hp (fp16 out)
    {
        GDescRaw dv = {};
        dv.A = ah + (size_t)BATCH * 1024; dv.lda = 1024; dv.rowperm = 0;
        dv.BT = Whp; dv.ldb = 1024; dv.nk = 1024 / BK;
        dv.N = 1024; dv.grid_n = 8;
        dv.out_f16 = V + (size_t)BATCH * 1024;
        tc_gemm_raw<<<(11 * 1024 / 128) * 8, 256, SMEM_RAW>>>(dv);   // 704 CTAs
    }

    // 4) q1 matvec + step-1 elementwise (steps 0 and 1 are batch-degenerate)
    q1_kernel<<<192, 256>>>();
    step1_ew<<<(BATCH * 384 + 255) / 256, 256>>>();

    // 5) steps t=2..11, one launch each (256 CTAs, warp-split-K, 2 CTA/SM)
    for (int t = 2; t < TSTEPS; ++t)
        tc_step<<<256, 256, SMEM_STEP2>>>(t, out);
}

// round 17
// speedup vs baseline: 1.1145x; 1.1145x over previous
#include <cuda_runtime.h>
#include <cuda_fp16.h>
#include <cstdint>
#include <math.h>

#define BATCH 1024
#define TSTEPS 12
#define TAU 0.25f
#define BK 64                  // K halfs per pipeline stage
#define SROW 72                // smem row stride in halfs (144B), conflict-free
#define ASTG   (128 * SROW * 2) // 18432
#define ASTG64 (64 * SROW * 2)  // 9216
#define BSTG96 (96 * SROW * 2)
#define BSTG128 (128 * SROW * 2)

// ---------------- static scratch ----------------
__device__ __align__(256) __half g_Xh[(size_t)BATCH * TSTEPS * 1024];
__device__ __align__(256) __half g_Uh[(size_t)11 * BATCH * 1024];
__device__ __align__(256) __half g_V[(size_t)TSTEPS * BATCH * 1024];   // fp16 V
__device__ __align__(256) __half g_ah[TSTEPS][(size_t)BATCH * 1024];
__device__ __align__(256) __half g_apc[2][(size_t)BATCH * 1536];
__device__ __align__(256) float  g_psc[2][(size_t)BATCH * 1536];
__device__ __align__(256) __half g_Ws[(size_t)1536 * 1536];
__device__ __align__(256) __half g_Whp[(size_t)1024 * 1024];
__device__ __align__(256) __half g_Woh[(size_t)1024 * 1024];
__device__ __align__(256) float  g_biaspc[1536];
__device__ __align__(256) float  g_psc0[1536];
__device__ __align__(256) __half g_apc0h[1536];
__device__ __align__(256) float  g_q1[1536];

// ---------------- helpers ----------------
__device__ __forceinline__ uint32_t smem_u32(const void* p) {
    uint32_t a;
    asm("{ .reg .u64 t; cvta.to.shared.u64 t, %1; cvt.u32.u64 %0, t; }" : "=r"(a) : "l"(p));
    return a;
}
#define CP_ASYNC16(dst, src) \
    asm volatile("cp.async.cg.shared.global [%0], [%1], 16;" :: "r"(dst), "l"(src))
#define CP_COMMIT() asm volatile("cp.async.commit_group;" ::: "memory")
#define CP_WAIT(n)  asm volatile("cp.async.wait_group %0;" :: "n"(n) : "memory")

#define LDSM_X4(r0, r1, r2, r3, a) \
    asm volatile("ldmatrix.sync.aligned.m8n8.x4.shared.b16 {%0,%1,%2,%3}, [%4];" \
                 : "=r"(r0), "=r"(r1), "=r"(r2), "=r"(r3) : "r"(a))

__device__ __forceinline__ void mma_f16(float* d, const uint32_t* a, const uint32_t* b) {
    asm volatile(
        "mma.sync.aligned.m16n8k16.row.col.f32.f16.f16.f32 "
        "{%0,%1,%2,%3}, {%4,%5,%6,%7}, {%8,%9}, {%0,%1,%2,%3};"
        : "+f"(d[0]), "+f"(d[1]), "+f"(d[2]), "+f"(d[3])
        : "r"(a[0]), "r"(a[1]), "r"(a[2]), "r"(a[3]), "r"(b[0]), "r"(b[1]));
}
__device__ __forceinline__ float sigm(float x) { return 1.0f / (1.0f + expf(-x)); }

// ---------------- raw GEMM (128x128, 2-stage, 2 CTA/SM) — measured 77us ------
struct GDescRaw {
    const __half* A; int lda; int rowperm;
    const __half* BT; int ldb;
    int nk;
    int N; int grid_n;
    float* out_f32;
    __half* out_f16;
};

__global__ __launch_bounds__(256, 2)
void tc_gemm_raw(GDescRaw d) {
    extern __shared__ __align__(16) char smem[];
    const uint32_t sA = smem_u32(smem);
    const uint32_t sB = sA + 2 * ASTG;
    const int bm = blockIdx.x / d.grid_n;
    const int bn = blockIdx.x % d.grid_n;
    const int tid = threadIdx.x;
    const int warp = tid >> 5, lane = tid & 31;
    const int wm = warp >> 1, wn = warp & 1;
    const int g = lane >> 2, tg = lane & 3;

    const size_t arow = (size_t)bm * 128;
    const size_t brow = (size_t)bn * 128;

    float acc[2][8][4];
#pragma unroll
    for (int i = 0; i < 2; ++i)
#pragma unroll
        for (int j = 0; j < 8; ++j)
#pragma unroll
            for (int k = 0; k < 4; ++k) acc[i][j][k] = 0.0f;

    const int lrow = tid >> 3;
    const int lch  = (tid & 7) << 3;

    auto load_stage = [&](int kc, int s) {
        const int kbase = kc * BK;
#pragma unroll
        for (int i = 0; i < 4; ++i) {
            size_t r = arow + lrow + 32 * i;
            if (d.rowperm) { size_t b = r & 1023, t = r >> 10; r = b * 12 + t; }
            CP_ASYNC16(sA + s * ASTG + (uint32_t)((lrow + 32 * i) * SROW + lch) * 2u,
                       d.A + r * (size_t)d.lda + kbase + lch);
        }
#pragma unroll
        for (int i = 0; i < 4; ++i) {
            int r = lrow + 32 * i;
            CP_ASYNC16(sB + s * BSTG128 + (uint32_t)(r * SROW + lch) * 2u,
                       d.BT + (brow + r) * (size_t)d.ldb + kbase + lch);
        }
        CP_COMMIT();
    };

    const uint32_t aLane =
        (uint32_t)(((wm * 32) + (((lane >> 3) & 1) << 3) + (lane & 7)) * SROW +
                   ((lane >> 4) << 3)) * 2u;
    const uint32_t bLane =
        (uint32_t)(((wn * 64) + (((lane >> 4) & 1) << 3) + (lane & 7)) * SROW +
                   (((lane >> 3) & 1) << 3)) * 2u;

    auto compute_stage = [&](int s) {
        const uint32_t aOff = sA + s * ASTG + aLane;
        const uint32_t bOff = sB + s * BSTG128 + bLane;
#pragma unroll
        for (int k16 = 0; k16 < BK / 16; ++k16) {
            uint32_t af[2][4], bf[4][4];
#pragma unroll
            for (int mt = 0; mt < 2; ++mt)
                LDSM_X4(af[mt][0], af[mt][1], af[mt][2], af[mt][3],
                        aOff + mt * 16 * SROW * 2 + k16 * 32);
#pragma unroll
            for (int np = 0; np < 4; ++np)
                LDSM_X4(bf[np][0], bf[np][1], bf[np][2], bf[np][3],
                        bOff + np * 16 * SROW * 2 + k16 * 32);
#pragma unroll
            for (int mt = 0; mt < 2; ++mt)
#pragma unroll
                for (int nt = 0; nt < 8; ++nt)
                    mma_f16(acc[mt][nt], af[mt], &bf[nt >> 1][(nt & 1) * 2]);
        }
    };

    load_stage(0, 0);
    const int nk = d.nk;
    for (int kc = 0; kc < nk; ++kc) {
        if (kc + 1 < nk) {
            load_stage(kc + 1, (kc + 1) & 1);
            CP_WAIT(1);
        } else {
            CP_WAIT(0);
        }
        __syncthreads();
        compute_stage(kc & 1);
        __syncthreads();
    }

    const int N = d.N;
#pragma unroll
    for (int mt = 0; mt < 2; ++mt) {
        const int r0 = bm * 128 + wm * 32 + mt * 16 + g;
#pragma unroll
        for (int nt = 0; nt < 8; ++nt) {
            const int c0 = bn * 128 + wn * 64 + nt * 8 + tg * 2;
            if (d.out_f32) {
                float* o0 = d.out_f32 + (size_t)r0 * N + c0;
                *(float2*)o0 = make_float2(acc[mt][nt][0], acc[mt][nt][1]);
                *(float2*)(o0 + (size_t)8 * N) = make_float2(acc[mt][nt][2], acc[mt][nt][3]);
            } else {
                __half* o0 = d.out_f16 + (size_t)r0 * N + c0;
                *(__half2*)o0 = __floats2half2_rn(acc[mt][nt][0], acc[mt][nt][1]);
                *(__half2*)(o0 + (size_t)8 * N) = __floats2half2_rn(acc[mt][nt][2], acc[mt][nt][3]);
            }
        }
    }
}

// ---------------- balanced step kernel (t=2..11): 296 CTAs, matched pairs ----
// bids 0..135: full 64x96 p-tiles; 136..147: c-tiles; 148..227: half 32x96
// p-tiles (warp-split-K); 228..295: c-tiles. bid%148 pairing => max-load pairs
// are (full-p + c), ~17% lighter than the old p+p pairs.
__global__ __launch_bounds__(256, 2)
void tc_step(int t, float* __restrict__ out) {
    constexpr int NT = 6;
    extern __shared__ __align__(16) char smem[];
    const uint32_t sA = smem_u32(smem);                 // 2 x ASTG64
    const uint32_t sB = sA + 2 * ASTG64;                // 2 x BSTG96
    const int bid = blockIdx.x;

    int bn, bm, rowbase, nrows;
    if (bid < 128)      { bm = bid >> 3; bn = bid & 7; rowbase = bm * 64; nrows = 64; }
    else if (bid < 136) { bm = bid - 128; bn = 8; rowbase = bm * 64; nrows = 64; }
    else if (bid < 148) { int cid = bid - 136; bn = 11 + (cid >> 4); bm = cid & 15;
                          rowbase = bm * 64; nrows = 64; }
    else if (bid < 228) { int hid = bid - 148; int tt = hid >> 1, hf = hid & 1;
                          if (tt < 8)       { bn = 8;  bm = 8 + tt; }
                          else if (tt < 24) { bn = 9;  bm = tt - 8; }
                          else              { bn = 10; bm = tt - 24; }
                          rowbase = bm * 64 + hf * 32; nrows = 32; }
    else                { int cid = 12 + (bid - 228); bn = 11 + (cid >> 4); bm = cid & 15;
                          rowbase = bm * 64; nrows = 64; }

    const int tid = threadIdx.x;
    const int warp = tid >> 5, lane = tid & 31;
    const int wn = warp & 1;
    const int g = lane >> 2, tg = lane & 3;
    const int rd = t & 1, wr = rd ^ 1;
    const bool full = (nrows == 64);
    const int warpRow = full ? ((warp >> 1) * 16) : (((warp >> 1) & 1) * 16);
    const int wk   = full ? 0 : (warp >> 2);
    const int k0   = full ? 0 : (wk * 2);
    const int k16n = full ? 4 : 2;

    const __half* __restrict__ A = g_apc[rd];
    const size_t brow = (size_t)bn * 96;
    const int nk = (bn >= 11) ? 16 : 24;   // c-tiles skip zero K block

    float acc[NT][4];
#pragma unroll
    for (int j = 0; j < NT; ++j)
#pragma unroll
        for (int k = 0; k < 4; ++k) acc[j][k] = 0.0f;

    const int lrow = tid >> 3;           // 0..31
    const int lch  = (tid & 7) << 3;
    const int nAiter = full ? 2 : 1;

    auto load_stage = [&](int kc, int s) {
        const int kbase = kc * BK;
        for (int i = 0; i < nAiter; ++i) {
            int r = lrow + 32 * i;
            CP_ASYNC16(sA + s * ASTG64 + (uint32_t)(r * SROW + lch) * 2u,
                       A + (size_t)(rowbase + r) * 1536 + kbase + lch);
        }
#pragma unroll
        for (int i = 0; i < 3; ++i) {
            int r = lrow + 32 * i;
            CP_ASYNC16(sB + s * BSTG96 + (uint32_t)(r * SROW + lch) * 2u,
                       g_Ws + (brow + r) * (size_t)1536 + kbase + lch);
        }
        CP_COMMIT();
    };

    const uint32_t aLane =
        (uint32_t)((warpRow + (((lane >> 3) & 1) << 3) + (lane & 7)) * SROW +
                   ((lane >> 4) << 3)) * 2u;
    const uint32_t bLane =
        (uint32_t)(((wn * 48) + (((lane >> 4) & 1) << 3) + (lane & 7)) * SROW +
                   (((lane >> 3) & 1) << 3)) * 2u;

    auto compute_stage = [&](int s) {
        const uint32_t aOff = sA + s * ASTG64 + aLane;
        const uint32_t bOff = sB + s * BSTG96 + bLane;
#pragma unroll 4
        for (int j = 0; j < k16n; ++j) {
            const int k16 = k0 + j;
            uint32_t af[4], bf[3][4];
            LDSM_X4(af[0], af[1], af[2], af[3], aOff + k16 * 32);
#pragma unroll
            for (int np = 0; np < 3; ++np)
                LDSM_X4(bf[np][0], bf[np][1], bf[np][2], bf[np][3],
                        bOff + np * 16 * SROW * 2 + k16 * 32);
#pragma unroll
            for (int nt = 0; nt < NT; ++nt)
                mma_f16(acc[nt], af, &bf[nt >> 1][(nt & 1) * 2]);
        }
    };

    load_stage(0, 0);
    for (int kc = 0; kc < nk; ++kc) {
        if (kc + 1 < nk) {
            load_stage(kc + 1, (kc + 1) & 1);
            CP_WAIT(1);
        } else {
            CP_WAIT(0);
        }
        __syncthreads();
        compute_stage(kc & 1);
        __syncthreads();
    }

    // half tiles: cross-warp K reduction via smem (pipeline buffers are free now)
    float* rbuf = (float*)smem;          // 32 x 96, stride 100 floats
    if (!full) {
        if (wk == 1) {
#pragma unroll
            for (int nt = 0; nt < NT; ++nt)
#pragma unroll
                for (int h = 0; h < 2; ++h) {
                    int rl = warpRow + g + 8 * h;
                    int cl = wn * 48 + nt * 8 + tg * 2;
                    *(float2*)&rbuf[rl * 100 + cl] =
                        make_float2(acc[nt][2 * h + 0], acc[nt][2 * h + 1]);
                }
        }
        __syncthreads();
        if (wk == 1) return;
    }

    const __half* __restrict__ Vt = g_V + (size_t)t * (BATCH * 1024);
    const float* __restrict__ prev = g_psc[rd];
    float* __restrict__ st = g_psc[wr];
    __half* __restrict__ act = g_apc[wr];
    float* __restrict__ extra =
        (t >= TSTEPS - 4) ? out + (size_t)(t - (TSTEPS - 4)) * BATCH * 1024 : nullptr;

#pragma unroll
    for (int nt = 0; nt < NT; ++nt) {
        const int c0 = bn * 96 + wn * 48 + nt * 8 + tg * 2;
        const bool isP = c0 < 1024;
        float2 bv = *(const float2*)(g_biaspc + c0);
#pragma unroll
        for (int h = 0; h < 2; ++h) {
            const int rl = warpRow + g + 8 * h;
            const int r = rowbase + rl;
            float2 add = make_float2(0.f, 0.f);
            if (!full) add = *(const float2*)&rbuf[rl * 100 + (wn * 48 + nt * 8 + tg * 2)];
            const size_t off = (size_t)r * 1536 + c0;
            float2 pv = *(const float2*)(prev + off);
            float2 vv = make_float2(0.f, 0.f);
            if (isP) vv = __half22float2(*(const __half2*)(Vt + (size_t)r * 1024 + c0));
            float2 v, a;
            v.x = TAU * (acc[nt][2 * h + 0] + add.x + vv.x + bv.x) + (1.0f - TAU) * pv.x;
            v.y = TAU * (acc[nt][2 * h + 1] + add.y + vv.y + bv.y) + (1.0f - TAU) * pv.y;
            a.x = sigm(v.x);
            a.y = sigm(v.y);
            *(float2*)(st + off) = v;
            *(__half2*)(act + off) = __floats2half2_rn(a.x, a.y);
            if (extra && isP)
                *(float2*)(extra + (size_t)r * 1024 + c0) = a;
        }
    }
}

// ---------------- prep kernels ----------------
__global__ void prep_misc(const float* __restrict__ inputs,
                          const float* __restrict__ bias_p,
                          const float* __restrict__ bias_c) {
    int i = blockIdx.x * blockDim.x + threadIdx.x;
    const int n8 = BATCH * TSTEPS * 1024 / 8;
    if (i < n8) {
        float4 a = ((const float4*)inputs)[2 * i];
        float4 b = ((const float4*)inputs)[2 * i + 1];
        __half2 h0 = __floats2half2_rn(a.x, a.y);
        __half2 h1 = __floats2half2_rn(a.z, a.w);
        __half2 h2 = __floats2half2_rn(b.x, b.y);
        __half2 h3 = __floats2half2_rn(b.z, b.w);
        uint4 o;
        o.x = *(uint32_t*)&h0; o.y = *(uint32_t*)&h1;
        o.z = *(uint32_t*)&h2; o.w = *(uint32_t*)&h3;
        ((uint4*)g_Xh)[i] = o;
    }
    if (i < 1536) g_biaspc[i] = (i < 1024) ? bias_p[i] : bias_c[i - 1024];
    if (i < 512 * 512 / 8) {   // zero g_Ws c-rows, K in [1024,1536)
        int row = 1024 + (i >> 6);
        int col = 1024 + (i & 63) * 8;
        *(uint4*)(g_Ws + (size_t)row * 1536 + col) = make_uint4(0, 0, 0, 0);
    }
}

__global__ void prep_tr(const float* __restrict__ w_oh, const float* __restrict__ w_hp,
                        const float* __restrict__ w_pp, const float* __restrict__ w_pc,
                        const float* __restrict__ w_cp) {
    __shared__ float t[32][33];
    const int z = blockIdx.z;
    const float* src; __half* dst; int K, N, ldd, koff;
    switch (z) {
        case 0: src = w_oh; dst = g_Woh; K = 1024; N = 1024; ldd = 1024; koff = 0;    break;
        case 1: src = w_hp; dst = g_Whp; K = 1024; N = 1024; ldd = 1024; koff = 0;    break;
        case 2: src = w_pp; dst = g_Ws;  K = 1024; N = 1024; ldd = 1536; koff = 0;    break;
        case 3: src = w_cp; dst = g_Ws;  K =  512; N = 1024; ldd = 1536; koff = 1024; break;
        default: src = w_pc; dst = g_Ws + (size_t)1024 * 1536;
                 K = 1024; N = 512; ldd = 1536; koff = 0; break;
    }
    int n0 = blockIdx.x * 32, k0 = blockIdx.y * 32;
    if (n0 >= N || k0 >= K) return;
    int tx = threadIdx.x, ty = threadIdx.y;
#pragma unroll
    for (int i = 0; i < 4; ++i)
        t[ty + 8 * i][tx] = src[(size_t)(k0 + ty + 8 * i) * N + n0 + tx];
    __syncthreads();
#pragma unroll
    for (int i = 0; i < 4; ++i)
        dst[(size_t)(n0 + ty + 8 * i) * ldd + koff + k0 + tx] = __float2half_rn(t[tx][ty + 8 * i]);
}

// step-0 constants via row sums of the transposed fp16 weights (coalesced).
__global__ void colsum2_kernel() {
    int row = blockIdx.x * 8 + (threadIdx.x >> 5);
    int lane = threadIdx.x & 31;
    if (row >= 1536) return;
    const __half2* w = (const __half2*)(g_Ws + (size_t)row * 1536);
    float s = 0.f;
    for (int k = lane; k < 768; k += 32) {
        float2 wv = __half22float2(w[k]);
        s += wv.x + wv.y;
    }
    if (row < 1024) {
        const __half2* w2 = (const __half2*)(g_Whp + (size_t)row * 1024);
        for (int k = lane; k < 512; k += 32) {
            float2 wv = __half22float2(w2[k]);
            s += wv.x + wv.y;
        }
    }
#pragma unroll
    for (int o = 16; o; o >>= 1) s += __shfl_xor_sync(0xFFFFFFFFu, s, o);
    if (lane == 0) {
        float v = TAU * (0.5f * s + g_biaspc[row]);
        g_psc0[row] = v;
        g_apc0h[row] = __float2half_rn(sigm(v));
    }
}

// q1[n] = apc0 . Ws[n,:]  (warp per row)
__global__ void q1_kernel() {
    int row = blockIdx.x * 8 + (threadIdx.x >> 5);
    int lane = threadIdx.x & 31;
    if (row >= 1536) return;
    const __half2* w = (const __half2*)(g_Ws + (size_t)row * 1536);
    const __half2* a = (const __half2*)g_apc0h;
    float s = 0.f;
    for (int k = lane; k < 768; k += 32) {
        float2 wv = __half22float2(w[k]);
        float2 av = __half22float2(a[k]);
        s += wv.x * av.x + wv.y * av.y;
    }
#pragma unroll
    for (int o = 16; o; o >>= 1) s += __shfl_xor_sync(0xFFFFFFFFu, s, o);
    if (lane == 0) g_q1[row] = s;
}

// step 1 (elementwise)
__global__ void step1_ew() {
    int idx = blockIdx.x * blockDim.x + threadIdx.x;   // B*384
    if (idx >= BATCH * 384) return;
    int b = idx / 384, c4 = (idx % 384) * 4;
    float4 q = *(const float4*)(g_q1 + c4);
    float4 bi = *(const float4*)(g_biaspc + c4);
    float4 p0 = *(const float4*)(g_psc0 + c4);
    float4 vv = make_float4(0.f, 0.f, 0.f, 0.f);
    if (c4 < 1024) {
        uint2 vh = *(const uint2*)(g_V + (size_t)BATCH * 1024 + (size_t)b * 1024 + c4);
        float2 lo = __half22float2(*(const __half2*)&vh.x);
        float2 hi = __half22float2(*(const __half2*)&vh.y);
        vv = make_float4(lo.x, lo.y, hi.x, hi.y);
    }
    float4 v;
    v.x = TAU * (vv.x + q.x + bi.x) + (1.0f - TAU) * p0.x;
    v.y = TAU * (vv.y + q.y + bi.y) + (1.0f - TAU) * p0.y;
    v.z = TAU * (vv.z + q.z + bi.z) + (1.0f - TAU) * p0.z;
    v.w = TAU * (vv.w + q.w + bi.w) + (1.0f - TAU) * p0.w;
    *(float4*)(g_psc[0] + (size_t)b * 1536 + c4) = v;
    __half2 lo = __floats2half2_rn(sigm(v.x), sigm(v.y));
    __half2 hi = __floats2half2_rn(sigm(v.z), sigm(v.w));
    uint2 o; o.x = *(uint32_t*)&lo; o.y = *(uint32_t*)&hi;
    *(uint2*)(g_apc[0] + (size_t)b * 1536 + c4) = o;
}

// h-scan over fp16 U (t-major): slot t+1 <- sigmoid(h_t), t=0..10
__global__ void hscan_kernel(const float* __restrict__ bias_h) {
    int i = blockIdx.x * blockDim.x + threadIdx.x;   // B*128
    if (i >= BATCH * 128) return;
    int b = i >> 7, h8 = (i & 127) << 3;
    float bh[8];
    *(float4*)&bh[0] = *(const float4*)(bias_h + h8);
    *(float4*)&bh[4] = *(const float4*)(bias_h + h8 + 4);
    float hh[8];
#pragma unroll
    for (int j = 0; j < 8; ++j) hh[j] = 0.f;
#pragma unroll
    for (int t = 0; t < 11; ++t) {
        uint4 u4 = *(const uint4*)(g_Uh + ((size_t)(t * 1024 + b) << 10) + h8);
        const __half2* uh = (const __half2*)&u4;
        uint4 o;
        uint32_t* op = (uint32_t*)&o;
#pragma unroll
        for (int j = 0; j < 4; ++j) {
            float2 u = __half22float2(uh[j]);
            hh[2 * j + 0] = TAU * (u.x + bh[2 * j + 0]) + (1.0f - TAU) * hh[2 * j + 0];
            hh[2 * j + 1] = TAU * (u.y + bh[2 * j + 1]) + (1.0f - TAU) * hh[2 * j + 1];
            __half2 s = __floats2half2_rn(sigm(hh[2 * j + 0]), sigm(hh[2 * j + 1]));
            op[j] = *(uint32_t*)&s;
        }
        *(uint4*)(g_ah[t + 1] + (size_t)b * 1024 + h8) = o;
    }
}

// ---------------- launch ----------------
extern "C" void kernel_launch(void* const* d_in, const int* in_sizes, int n_in,
                              void* d_out, int out_size) {
    const float* inputs = (const float*)d_in[0];
    const float* w_oh   = (const float*)d_in[1];
    const float* w_hp   = (const float*)d_in[2];
    const float* w_pp   = (const float*)d_in[3];
    const float* w_pc   = (const float*)d_in[4];
    const float* w_cp   = (const float*)d_in[5];
    const float* bias_h = (const float*)d_in[6];
    const float* bias_p = (const float*)d_in[7];
    const float* bias_c = (const float*)d_in[8];
    float* out = (float*)d_out;                    // [4, B, 1024]

    __half *Xh, *Uh, *ah, *V, *Whp, *Woh;
    cudaGetSymbolAddress((void**)&Xh,  g_Xh);
    cudaGetSymbolAddress((void**)&Uh,  g_Uh);
    cudaGetSymbolAddress((void**)&ah,  g_ah);
    cudaGetSymbolAddress((void**)&V,   g_V);
    cudaGetSymbolAddress((void**)&Whp, g_Whp);
    cudaGetSymbolAddress((void**)&Woh, g_Woh);

    const int SMEM_RAW  = 2 * (ASTG + BSTG128);    // 73728
    const int SMEM_STEP = 2 * (ASTG64 + BSTG96);   // 46080
    cudaFuncSetAttribute(tc_gemm_raw, cudaFuncAttributeMaxDynamicSharedMemorySize, SMEM_RAW);
    cudaFuncSetAttribute(tc_step, cudaFuncAttributeMaxDynamicSharedMemorySize, SMEM_STEP);

    // 0) prep
    prep_misc<<<(BATCH * TSTEPS * 1024 / 8 + 255) / 256, 256>>>(inputs, bias_p, bias_c);
    prep_tr<<<dim3(32, 32, 5), dim3(32, 8)>>>(w_oh, w_hp, w_pp, w_pc, w_cp);
    colsum2_kernel<<<192, 256>>>();

    // 1) U GEMM (t-major rows t*1024+b, t=0..10): Uh = Xh @ w_oh, fp16 out
    {
        GDescRaw du = {};
        du.A = Xh; du.lda = 1024; du.rowperm = 1;
        du.BT = Woh; du.ldb = 1024; du.nk = 1024 / BK;
        du.N = 1024; du.grid_n = 8;
        du.out_f16 = Uh;
        tc_gemm_raw<<<(11 * 1024 / 128) * 8, 256, SMEM_RAW>>>(du);   // 704 CTAs
    }

    // 2) h-scan -> a_h slots 1..11
    hscan_kernel<<<(BATCH * 128 + 255) / 256, 256>>>(bias_h);

    // 3) V GEMM for t=1..11: V[t] = ah[slot t] @ w_hp (fp16 out)
    {
        GDescRaw dv = {};
        dv.A = ah + (size_t)BATCH * 1024; dv.lda = 1024; dv.rowperm = 0;
        dv.BT = Whp; dv.ldb = 1024; dv.nk = 1024 / BK;
        dv.N = 1024; dv.grid_n = 8;
        dv.out_f16 = V + (size_t)BATCH * 1024;
        tc_gemm_raw<<<(11 * 1024 / 128) * 8, 256, SMEM_RAW>>>(dv);   // 704 CTAs
    }

    // 4) q1 matvec + step-1 elementwise (steps 0 and 1 are batch-degenerate)
    q1_kernel<<<192, 256>>>();
    step1_ew<<<(BATCH * 384 + 255) / 256, 256>>>();

    // 5) steps t=2..11: balanced 296-CTA grid, matched heavy/light pairing
    for (int t = 2; t < TSTEPS; ++t)
        tc_step<<<296, 256, SMEM_STEP>>>(t, out);
}